// round 13
// baseline (speedup 1.0000x reference)
#include <cuda_runtime.h>

#define NCLS 10
#define DD   128
#define WPB  4                    // warps per block
#define TPB  (WPB * 32)           // 128 threads
#define NBLK 740                  // 5 blocks/SM * 148 SMs, 20 warps/SM

// per-warp STAGING layout (floats) — written once at end of kernel, no RMW:
//   [0, 1280)        sums[10][128]
//   [1280, 1600)     rssq partials [10][32]  (per lane)
//   [1600, 1610)     counts[10]              (lane 0 only)
#define W_RSSQ (NCLS * DD)            // 1280
#define W_CNT  (W_RSSQ + NCLS * 32)   // 1600
#define WSTP   1616                   // floats per warp region (6464 B)

#define ONE2 0x3F8000003F800000ULL    // packed {1.0f, 1.0f}

// Zero-initialized at module load; the finalizing block re-zeros everything
// after each use, so every graph replay starts from clean state.
__device__ float g_sums[NCLS * DD];
__device__ float g_rssq[NCLS];
__device__ float g_cnt[NCLS];
__device__ unsigned int g_ticket;

__device__ __forceinline__ unsigned long long fma2(unsigned long long a,
                                                   unsigned long long b,
                                                   unsigned long long c) {
    unsigned long long d;
    asm("fma.rn.f32x2 %0, %1, %2, %3;" : "=l"(d) : "l"(a), "l"(b), "l"(c));
    return d;
}
__device__ __forceinline__ unsigned long long mul2(unsigned long long a,
                                                   unsigned long long b) {
    unsigned long long d;
    asm("mul.rn.f32x2 %0, %1, %2;" : "=l"(d) : "l"(a), "l"(b));
    return d;
}
__device__ __forceinline__ unsigned long long pk(float lo, float hi) {
    unsigned long long d;
    asm("mov.b64 %0, {%1, %2};" : "=l"(d) : "f"(lo), "f"(hi));
    return d;
}
__device__ __forceinline__ void upk(float& lo, float& hi, unsigned long long v) {
    asm("mov.b64 {%0, %1}, %2;" : "=f"(lo), "=f"(hi) : "l"(v));
}

__global__ __launch_bounds__(TPB, 5) void acc_k(const float4* __restrict__ x4,
                                                const int* __restrict__ t,
                                                int n,
                                                float* __restrict__ out) {
    __shared__ __align__(16) float sm[WPB * WSTP];
    __shared__ bool s_last;
    const int lane = threadIdx.x & 31;
    const int warp = threadIdx.x >> 5;
    float* ws = sm + warp * WSTP;

    // ── register accumulators: zero smem in the hot loop ──
    unsigned long long s01[NCLS], s23[NCLS], rc[NCLS];
#pragma unroll
    for (int c = 0; c < NCLS; c++) { s01[c] = 0ULL; s23[c] = 0ULL; rc[c] = 0ULL; }

    // contiguous per-warp chunk (chunk even keeps int2 t-loads aligned)
    const int gw = blockIdx.x * WPB + warp;   // global warp id
    const int W  = NBLK * WPB;                // 2960 warps
    int chunk = (n + W - 1) / W;
    chunk = (chunk + 1) & ~1;
    const int start = gw * chunk;
    const int end   = (start + chunk < n) ? (start + chunk) : n;

#define ROW(tt, vv) do {                                                    \
        unsigned long long v01_ = pk(vv.x, vv.y);                           \
        unsigned long long v23_ = pk(vv.z, vv.w);                           \
        unsigned long long p2_  = mul2(v01_, v01_);                         \
        p2_ = fma2(v23_, v23_, p2_);                                        \
        float pa_, pb_; upk(pa_, pb_, p2_);                                 \
        unsigned long long pc_ = pk(pa_ + pb_, 1.0f);                       \
        _Pragma("unroll")                                                   \
        for (int c_ = 0; c_ < NCLS; c_++) {                                 \
            unsigned long long ind_ = ((tt) == c_) ? ONE2 : 0ULL;           \
            s01[c_] = fma2(v01_, ind_, s01[c_]);                            \
            s23[c_] = fma2(v23_, ind_, s23[c_]);                            \
            rc[c_]  = fma2(pc_,  ind_, rc[c_]);                             \
        }                                                                   \
    } while (0)

    int i = start;
    const int len = (end - start > 0) ? (end - start) : 0;
    const int nfull = len / 2;
    if (nfull > 0) {
        const float4* xp = x4 + (size_t)start * 32 + lane;

        // U=2 double-buffer: next pair's loads in flight while current pair
        // is folded into registers (pure FMA work, no memory in the chain).
        int2   ta = *reinterpret_cast<const int2*>(t + i);
        float4 a0 = __ldcs(xp + 0 * 32);
        float4 a1 = __ldcs(xp + 1 * 32);

        for (int b = 1; b < nfull; b++) {
            xp += 2 * 32;
            int2   tb = *reinterpret_cast<const int2*>(t + i + 2);
            float4 b0 = __ldcs(xp + 0 * 32);
            float4 b1 = __ldcs(xp + 1 * 32);

            ROW(ta.x, a0); ROW(ta.y, a1);

            ta = tb; a0 = b0; a1 = b1;
            i += 2;
        }
        ROW(ta.x, a0); ROW(ta.y, a1);
        i += 2;
    }
    for (; i < end; i++) {
        int    tt = t[i];
        float4 vv = __ldcs(x4 + (size_t)i * 32 + lane);
        ROW(tt, vv);
    }
#undef ROW

    // ── stage registers into per-warp smem (write-only, once) ──
#pragma unroll
    for (int c = 0; c < NCLS; c++) {
        float a, b, cc, d;
        upk(a, b, s01[c]);
        upk(cc, d, s23[c]);
        float4 v4s = make_float4(a, b, cc, d);
        reinterpret_cast<float4*>(ws + c * DD)[lane] = v4s;
        float rlo, rhi;
        upk(rlo, rhi, rc[c]);
        ws[W_RSSQ + c * 32 + lane] = rlo;
        if (lane == 0) ws[W_CNT + c] = rhi;   // count (identical in all lanes)
    }
    __syncthreads();

    // combine the WPB warp-private copies, flush once per block
    for (int idx = threadIdx.x; idx < NCLS * DD; idx += TPB) {
        float s = 0.0f;
#pragma unroll
        for (int w = 0; w < WPB; w++) s += sm[w * WSTP + idx];
        atomicAdd(&g_sums[idx], s);
    }
    if (threadIdx.x < NCLS) {
        int c = threadIdx.x;
        float r = 0.0f, cn = 0.0f;
#pragma unroll
        for (int w = 0; w < WPB; w++) {
            for (int l = 0; l < 32; l++) r += sm[w * WSTP + W_RSSQ + c * 32 + l];
            cn += sm[w * WSTP + W_CNT + c];
        }
        atomicAdd(&g_rssq[c], r);
        atomicAdd(&g_cnt[c], cn);
    }

    // ── last-block finalization (fused; no second launch) ──
    __threadfence();
    if (threadIdx.x == 0)
        s_last = (atomicAdd(&g_ticket, 1u) == (unsigned)(gridDim.x - 1));
    __syncthreads();
    if (!s_last) return;

    // reuse the first NCLS floats of sm as cross[c] = ||sums[c]||^2
    float* cross = sm;
    if (threadIdx.x < NCLS) cross[threadIdx.x] = 0.0f;
    __syncthreads();
    {
        const int d = threadIdx.x;   // 128 threads, one per feature
#pragma unroll
        for (int c = 0; c < NCLS; c++) {
            float s = g_sums[c * DD + d];
            atomicAdd(&cross[c], s * s);
            g_sums[c * DD + d] = 0.0f;   // re-zero for next replay
        }
    }
    __syncthreads();
    if (threadIdx.x == 0) {
        float acc = 0.0f;
#pragma unroll
        for (int c = 0; c < NCLS; c++) {
            float nc = g_cnt[c];
            acc += (g_rssq[c] - cross[c] / nc) / (nc - 1.0f);
            g_rssq[c] = 0.0f;
            g_cnt[c]  = 0.0f;
        }
        out[0] = acc / (float)NCLS;
        g_ticket = 0u;
    }
}

extern "C" void kernel_launch(void* const* d_in, const int* in_sizes, int n_in,
                              void* d_out, int out_size) {
    const float4* x4 = (const float4*)d_in[0];   // x: [N, 128] fp32
    const int*    t  = (const int*)d_in[1];      // t: [N] int32
    const int n = in_sizes[1];                   // N = row count

    acc_k<<<NBLK, TPB>>>(x4, t, n, (float*)d_out);
}